// round 1
// baseline (speedup 1.0000x reference)
#include <cuda_runtime.h>

#define NPOINTS 100000
#define BATCH   4096
#define KSEL    10
#define TILE    8192          // points per smem tile (8192 * 16B = 128 KB)
#define NWARPS  8
#define RPW     4             // rays per warp
#define THREADS 256

static __device__ __forceinline__ float sigmoidf_(float x) {
    return 1.0f / (1.0f + expf(-x));
}

__global__ __launch_bounds__(THREADS, 1)
void gsplat_topk_kernel(const float* __restrict__ rays_o,
                        const float* __restrict__ rays_d,
                        const float* __restrict__ xyz,
                        const float* __restrict__ fdc,
                        const float* __restrict__ opacity,
                        float* __restrict__ out)
{
    extern __shared__ float4 tile[];   // TILE entries of (x, y, z, |p|^2)

    const int tid  = threadIdx.x;
    const int lane = tid & 31;
    const int wid  = tid >> 5;
    const int group = blockIdx.x * NWARPS + wid;   // 0..1023
    const int ray0  = group * RPW;

    const float POSINF = __int_as_float(0x7f800000);

    // ---- per-ray setup (replicated across lanes) ----
    float a[RPW], b[RPW], c[RPW], cn2[RPW], thr[RPW];
    float hd[RPW][KSEL];
    int   hi[RPW][KSEL];
    #pragma unroll
    for (int r = 0; r < RPW; r++) {
        int ray = ray0 + r;
        float ox = rays_o[3*ray+0], oy = rays_o[3*ray+1], oz = rays_o[3*ray+2];
        float dx = rays_d[3*ray+0], dy = rays_d[3*ray+1], dz = rays_d[3*ray+2];
        float cx = fmaf(dx, 3.0f, ox);
        float cy = fmaf(dy, 3.0f, oy);
        float cz = fmaf(dz, 3.0f, oz);
        a[r] = -2.0f * cx;
        b[r] = -2.0f * cy;
        c[r] = -2.0f * cz;
        cn2[r] = cx*cx + cy*cy + cz*cz;
        thr[r] = POSINF;
        #pragma unroll
        for (int j = 0; j < KSEL; j++) { hd[r][j] = POSINF; hi[r][j] = 0; }
    }

    // ---- scan all points in smem tiles ----
    for (int t0 = 0; t0 < NPOINTS; t0 += TILE) {
        __syncthreads();   // previous tile fully consumed
        // cooperative load: (x,y,z,p^2); pad with p^2=+INF so hot loop is unguarded
        for (int s = tid; s < TILE; s += THREADS) {
            int g = t0 + s;
            float4 v;
            if (g < NPOINTS) {
                float px = xyz[3*g+0], py = xyz[3*g+1], pz = xyz[3*g+2];
                v = make_float4(px, py, pz, fmaf(px, px, fmaf(py, py, pz*pz)));
            } else {
                v = make_float4(0.f, 0.f, 0.f, POSINF);
            }
            tile[s] = v;
        }
        __syncthreads();

        const float4* tp = tile + lane;
        #pragma unroll 4
        for (int j = 0; j < TILE/32; j++) {
            float4 p = tp[j*32];
            int gi = t0 + j*32 + lane;
            float key[RPW];
            #pragma unroll
            for (int r = 0; r < RPW; r++)
                key[r] = fmaf(p.x, a[r], fmaf(p.y, b[r], fmaf(p.z, c[r], p.w)));

            bool q0 = key[0] < thr[0];
            bool q1 = key[1] < thr[1];
            bool q2 = key[2] < thr[2];
            bool q3 = key[3] < thr[3];
            if (__any_sync(0xffffffffu, q0 | q1 | q2 | q3)) {
                // rare path: convergent replicated insertion (all lanes identical)
                #pragma unroll
                for (int r = 0; r < RPW; r++) {
                    unsigned mr = __ballot_sync(0xffffffffu, key[r] < thr[r]);
                    while (mr) {
                        int src = __ffs(mr) - 1;
                        mr &= mr - 1;
                        float kv = __shfl_sync(0xffffffffu, key[r], src);
                        int   ki = __shfl_sync(0xffffffffu, gi,     src);
                        if (kv < thr[r]) {         // warp-uniform
                            float v = kv; int vi = ki;
                            #pragma unroll
                            for (int jj = 0; jj < KSEL; jj++) {
                                if (v < hd[r][jj]) {
                                    float tv = hd[r][jj]; hd[r][jj] = v;  v  = tv;
                                    int   ti = hi[r][jj]; hi[r][jj] = vi; vi = ti;
                                }
                            }
                            thr[r] = hd[r][KSEL-1];
                        }
                    }
                }
            }
        }
    }

    // ---- epilogue: every lane holds the exact sorted top-10 per ray ----
    #pragma unroll
    for (int r = 0; r < RPW; r++) {
        float ws = 0.f, s0 = 0.f, s1 = 0.f, s2 = 0.f;
        #pragma unroll
        for (int k = 0; k < KSEL; k++) {
            float sq = hd[r][k] + cn2[r];
            float dist = sqrtf(fmaxf(sq, 0.0f));
            int id = hi[r][k];
            float op = opacity[id];
            float w = expf(-0.1f * dist) * sigmoidf_(op);
            ws += w;
            float f0 = fdc[3*id+0], f1 = fdc[3*id+1], f2 = fdc[3*id+2];
            s0 = fmaf(w, sigmoidf_(f0), s0);
            s1 = fmaf(w, sigmoidf_(f1), s1);
            s2 = fmaf(w, sigmoidf_(f2), s2);
        }
        if (lane == 0) {
            float inv = 1.0f / (ws + 1e-8f);
            int ray = ray0 + r;
            out[3*ray+0] = s0 * inv;
            out[3*ray+1] = s1 * inv;
            out[3*ray+2] = s2 * inv;
        }
    }
}

extern "C" void kernel_launch(void* const* d_in, const int* in_sizes, int n_in,
                              void* d_out, int out_size)
{
    const float* rays_o  = (const float*)d_in[0];
    const float* rays_d  = (const float*)d_in[1];
    const float* xyz     = (const float*)d_in[2];
    const float* fdc     = (const float*)d_in[3];
    const float* opacity = (const float*)d_in[4];
    float* out = (float*)d_out;

    const int smem = TILE * sizeof(float4);   // 128 KB
    static bool attr_set = false;
    if (!attr_set) {
        cudaFuncSetAttribute(gsplat_topk_kernel,
                             cudaFuncAttributeMaxDynamicSharedMemorySize, smem);
        attr_set = true;
    }

    dim3 grid(BATCH / (NWARPS * RPW * 4) * 4);   // 4096 / 32 = 128 blocks
    dim3 block(THREADS);
    gsplat_topk_kernel<<<grid, block, smem>>>(rays_o, rays_d, xyz, fdc, opacity, out);
}

// round 2
// speedup vs baseline: 1.2517x; 1.2517x over previous
#include <cuda_runtime.h>

#define NPOINTS 100000
#define BATCH   4096
#define KSEL    10
#define TILE    8192          // points per smem tile (8192 * 16B = 128 KB)
#define NWARPS  16
#define RPW     2             // rays per warp
#define THREADS 512

static __device__ __forceinline__ float sigmoidf_(float x) {
    return 1.0f / (1.0f + expf(-x));
}

__global__ __launch_bounds__(THREADS, 1)
void gsplat_topk_kernel(const float* __restrict__ rays_o,
                        const float* __restrict__ rays_d,
                        const float* __restrict__ xyz,
                        const float* __restrict__ fdc,
                        const float* __restrict__ opacity,
                        float* __restrict__ out)
{
    extern __shared__ float4 tile[];   // TILE entries of (x, y, z, |p|^2)

    const int tid  = threadIdx.x;
    const int lane = tid & 31;
    const int wid  = tid >> 5;
    const int ray0 = (blockIdx.x * NWARPS + wid) * RPW;

    const float POSINF = __int_as_float(0x7f800000);

    // ---- per-ray setup (replicated across all 32 lanes) ----
    float a0, b0, c0, cn20, a1, b1, c1, cn21;
    {
        int r0 = ray0, r1 = ray0 + 1;
        float ox = rays_o[3*r0+0], oy = rays_o[3*r0+1], oz = rays_o[3*r0+2];
        float dx = rays_d[3*r0+0], dy = rays_d[3*r0+1], dz = rays_d[3*r0+2];
        float cx = fmaf(dx, 3.0f, ox), cy = fmaf(dy, 3.0f, oy), cz = fmaf(dz, 3.0f, oz);
        a0 = -2.0f*cx; b0 = -2.0f*cy; c0 = -2.0f*cz;
        cn20 = cx*cx + cy*cy + cz*cz;
        ox = rays_o[3*r1+0]; oy = rays_o[3*r1+1]; oz = rays_o[3*r1+2];
        dx = rays_d[3*r1+0]; dy = rays_d[3*r1+1]; dz = rays_d[3*r1+2];
        cx = fmaf(dx, 3.0f, ox); cy = fmaf(dy, 3.0f, oy); cz = fmaf(dz, 3.0f, oz);
        a1 = -2.0f*cx; b1 = -2.0f*cy; c1 = -2.0f*cz;
        cn21 = cx*cx + cy*cy + cz*cz;
    }

    float thr0 = POSINF, thr1 = POSINF;
    float hd0[KSEL], hd1[KSEL];
    int   hi0[KSEL], hi1[KSEL];
    #pragma unroll
    for (int j = 0; j < KSEL; j++) {
        hd0[j] = POSINF; hd1[j] = POSINF; hi0[j] = 0; hi1[j] = 0;
    }

    // ---- scan all points in smem tiles ----
    for (int t0 = 0; t0 < NPOINTS; t0 += TILE) {
        __syncthreads();   // previous tile fully consumed
        for (int s = tid; s < TILE; s += THREADS) {
            int g = t0 + s;
            float4 v;
            if (g < NPOINTS) {
                float px = xyz[3*g+0], py = xyz[3*g+1], pz = xyz[3*g+2];
                v = make_float4(px, py, pz, fmaf(px, px, fmaf(py, py, pz*pz)));
            } else {
                v = make_float4(0.f, 0.f, 0.f, POSINF);
            }
            tile[s] = v;
        }
        __syncthreads();

        const float4* tp = tile + lane;
        #pragma unroll 4
        for (int j = 0; j < TILE/32; j++) {
            float4 p = tp[j*32];
            float k0 = fmaf(p.x, a0, fmaf(p.y, b0, fmaf(p.z, c0, p.w)));
            float k1 = fmaf(p.x, a1, fmaf(p.y, b1, fmaf(p.z, c1, p.w)));
            bool q0 = k0 < thr0;
            bool q1 = k1 < thr1;
            if (__any_sync(0xffffffffu, q0 | q1)) {
                // rare path: convergent replicated insertion (all lanes identical)
                int gi = t0 + j*32 + lane;
                unsigned m0 = __ballot_sync(0xffffffffu, k0 < thr0);
                while (m0) {
                    int src = __ffs(m0) - 1;
                    m0 &= m0 - 1;
                    float kv = __shfl_sync(0xffffffffu, k0, src);
                    int   ki = __shfl_sync(0xffffffffu, gi, src);
                    if (kv < thr0) {       // warp-uniform
                        float v = kv; int vi = ki;
                        #pragma unroll
                        for (int jj = 0; jj < KSEL; jj++) {
                            if (v < hd0[jj]) {
                                float tv = hd0[jj]; hd0[jj] = v;  v  = tv;
                                int   ti = hi0[jj]; hi0[jj] = vi; vi = ti;
                            }
                        }
                        thr0 = hd0[KSEL-1];
                    }
                }
                unsigned m1 = __ballot_sync(0xffffffffu, k1 < thr1);
                while (m1) {
                    int src = __ffs(m1) - 1;
                    m1 &= m1 - 1;
                    float kv = __shfl_sync(0xffffffffu, k1, src);
                    int   ki = __shfl_sync(0xffffffffu, gi, src);
                    if (kv < thr1) {
                        float v = kv; int vi = ki;
                        #pragma unroll
                        for (int jj = 0; jj < KSEL; jj++) {
                            if (v < hd1[jj]) {
                                float tv = hd1[jj]; hd1[jj] = v;  v  = tv;
                                int   ti = hi1[jj]; hi1[jj] = vi; vi = ti;
                            }
                        }
                        thr1 = hd1[KSEL-1];
                    }
                }
            }
        }
    }

    // ---- epilogue: every lane holds the exact sorted top-10 per ray ----
    if (lane == 0) {
        #pragma unroll
        for (int r = 0; r < RPW; r++) {
            const float* hd = (r == 0) ? hd0 : hd1;
            const int*   hi = (r == 0) ? hi0 : hi1;
            float cn2 = (r == 0) ? cn20 : cn21;
            float ws = 0.f, s0 = 0.f, s1 = 0.f, s2 = 0.f;
            #pragma unroll
            for (int k = 0; k < KSEL; k++) {
                float sq = hd[k] + cn2;
                float dist = sqrtf(fmaxf(sq, 0.0f));
                int id = hi[k];
                float op = opacity[id];
                float w = expf(-0.1f * dist) * sigmoidf_(op);
                ws += w;
                float f0 = fdc[3*id+0], f1 = fdc[3*id+1], f2 = fdc[3*id+2];
                s0 = fmaf(w, sigmoidf_(f0), s0);
                s1 = fmaf(w, sigmoidf_(f1), s1);
                s2 = fmaf(w, sigmoidf_(f2), s2);
            }
            float inv = 1.0f / (ws + 1e-8f);
            int ray = ray0 + r;
            out[3*ray+0] = s0 * inv;
            out[3*ray+1] = s1 * inv;
            out[3*ray+2] = s2 * inv;
        }
    }
}

extern "C" void kernel_launch(void* const* d_in, const int* in_sizes, int n_in,
                              void* d_out, int out_size)
{
    const float* rays_o  = (const float*)d_in[0];
    const float* rays_d  = (const float*)d_in[1];
    const float* xyz     = (const float*)d_in[2];
    const float* fdc     = (const float*)d_in[3];
    const float* opacity = (const float*)d_in[4];
    float* out = (float*)d_out;

    const int smem = TILE * sizeof(float4);   // 128 KB
    static bool attr_set = false;
    if (!attr_set) {
        cudaFuncSetAttribute(gsplat_topk_kernel,
                             cudaFuncAttributeMaxDynamicSharedMemorySize, smem);
        attr_set = true;
    }

    dim3 grid(BATCH / (NWARPS * RPW));   // 128 blocks
    dim3 block(THREADS);
    gsplat_topk_kernel<<<grid, block, smem>>>(rays_o, rays_d, xyz, fdc, opacity, out);
}